// round 4
// baseline (speedup 1.0000x reference)
#include <cuda_runtime.h>

#define N_SAMP 256
#define IN_F   1024
#define B_F    128
#define C_F    16
#define J_F    (B_F * C_F)   // 2048
#define OUT_W  (IN_F + B_F)  // 1152

// Scratch: mat[b][n][c], fp32, 2 MB
__device__ float g_mat[B_F * N_SAMP * C_F];

// ---------------------------------------------------------------------------
// Copy x into out[:, 0:1024] (float4 vectorized; out row stride 1152 floats,
// 4608 B, 16B-aligned)
// ---------------------------------------------------------------------------
__global__ __launch_bounds__(256) void copy_kernel(const float* __restrict__ x,
                                                   float* __restrict__ out) {
    int idx = blockIdx.x * 256 + threadIdx.x;   // float4 index, 256*256 total
    int n  = idx >> 8;                           // 256 float4 per row
    int c4 = idx & 255;
    ((float4*)(out + n * OUT_W))[c4] = ((const float4*)(x + n * IN_F))[c4];
}

// ---------------------------------------------------------------------------
// SGEMM: C[n][j] = sum_i x[n][i] * T[i][j]   (T viewed as [1024][2048])
// BM=64, BN=64, BK=16, 256 threads, 4x4 register tile per thread.
// Output scattered into g_mat[b][n][c] with b=j>>4, c=j&15.
// ---------------------------------------------------------------------------
#define BM 64
#define BN 64
#define BK 16
#define TM 4
#define TN 4

__global__ __launch_bounds__(256) void gemm_kernel(const float* __restrict__ x,
                                                   const float* __restrict__ T) {
    __shared__ float As[BK][BM + 4];
    __shared__ float Bs[BK][BN + 4];

    const int bm  = blockIdx.y;
    const int bn  = blockIdx.x;
    const int tid = threadIdx.x;
    const int tx  = tid & 15;      // 0..15
    const int ty  = tid >> 4;      // 0..15

    // A-tile load mapping: 64 rows x 16 cols, one float4 per thread
    const int arow  = tid >> 2;          // 0..63
    const int acol4 = (tid & 3) * 4;     // 0,4,8,12
    // B-tile load mapping: 16 rows x 64 cols, one float4 per thread
    const int brow  = tid >> 4;          // 0..15
    const int bcol4 = (tid & 15) * 4;    // 0..60

    const float* Ab = x + (bm * BM) * IN_F;
    const float* Bb = T + bn * BN;

    float acc[TM][TN] = {};

    for (int kt = 0; kt < IN_F; kt += BK) {
        float4 a = *(const float4*)(Ab + arow * IN_F + kt + acol4);
        As[acol4 + 0][arow] = a.x;
        As[acol4 + 1][arow] = a.y;
        As[acol4 + 2][arow] = a.z;
        As[acol4 + 3][arow] = a.w;
        *(float4*)&Bs[brow][bcol4] =
            *(const float4*)(Bb + (kt + brow) * J_F + bcol4);
        __syncthreads();

        #pragma unroll
        for (int k = 0; k < BK; k++) {
            float ar[TM], br[TN];
            #pragma unroll
            for (int i = 0; i < TM; i++) ar[i] = As[k][ty * TM + i];
            #pragma unroll
            for (int j = 0; j < TN; j++) br[j] = Bs[k][tx * TN + j];
            #pragma unroll
            for (int i = 0; i < TM; i++)
                #pragma unroll
                for (int j = 0; j < TN; j++)
                    acc[i][j] = fmaf(ar[i], br[j], acc[i][j]);
        }
        __syncthreads();
    }

    #pragma unroll
    for (int i = 0; i < TM; i++) {
        const int n = bm * BM + ty * TM + i;
        #pragma unroll
        for (int j = 0; j < TN; j++) {
            const int jj = bn * BN + tx * TN + j;
            const int b  = jj >> 4;
            const int c  = jj & 15;
            g_mat[b * (N_SAMP * C_F) + n * C_F + c] = acc[i][j];
        }
    }
}

// ---------------------------------------------------------------------------
// Pairwise: o[n,b] = sum_m exp(-sum_c |mat[n,b,c]-mat[m,b,c]|)
// Grid (B_F, 8): each block handles one b and 32 n's. 256 threads =
// 32 n-lanes x 8 m-slices. All lanes of a warp share m -> broadcast LDS,
// warp-uniform exp skip (d >= 40 -> exp(-d) < 5e-18, negligible vs o >= 1).
// ---------------------------------------------------------------------------
__global__ __launch_bounds__(256) void pair_kernel(float* __restrict__ out) {
    __shared__ float sm[N_SAMP][C_F];    // 16 KB: mat[b][:][:]
    __shared__ float red[8][33];

    const int b   = blockIdx.x;
    const int nt  = blockIdx.y;          // 0..7
    const int tid = threadIdx.x;
    const float* mb = g_mat + b * (N_SAMP * C_F);

    #pragma unroll
    for (int r = 0; r < 4; r++) {
        int i = tid + r * 256;           // float4 index, 1024 total
        ((float4*)sm)[i] = ((const float4*)mb)[i];
    }
    __syncthreads();

    const int tn = tid & 31;             // n lane
    const int tm = tid >> 5;             // m slice 0..7
    const int n  = nt * 32 + tn;

    float mine[C_F];
    #pragma unroll
    for (int c = 0; c < C_F; c++) mine[c] = sm[n][c];

    float acc = 0.f;
    for (int m = tm; m < N_SAMP; m += 8) {
        const float4 v0 = *(const float4*)&sm[m][0];
        const float4 v1 = *(const float4*)&sm[m][4];
        const float4 v2 = *(const float4*)&sm[m][8];
        const float4 v3 = *(const float4*)&sm[m][12];
        float d = 0.f;
        d += fabsf(mine[0]  - v0.x); d += fabsf(mine[1]  - v0.y);
        d += fabsf(mine[2]  - v0.z); d += fabsf(mine[3]  - v0.w);
        d += fabsf(mine[4]  - v1.x); d += fabsf(mine[5]  - v1.y);
        d += fabsf(mine[6]  - v1.z); d += fabsf(mine[7]  - v1.w);
        d += fabsf(mine[8]  - v2.x); d += fabsf(mine[9]  - v2.y);
        d += fabsf(mine[10] - v2.z); d += fabsf(mine[11] - v2.w);
        d += fabsf(mine[12] - v3.x); d += fabsf(mine[13] - v3.y);
        d += fabsf(mine[14] - v3.z); d += fabsf(mine[15] - v3.w);
        if (d < 40.f) acc += __expf(-d);   // includes self term exp(0)=1
    }
    red[tm][tn] = acc;
    __syncthreads();

    if (tm == 0) {
        float s = acc;
        #pragma unroll
        for (int t = 1; t < 8; t++) s += red[t][tn];
        out[n * OUT_W + IN_F + b] = s;
    }
}

// ---------------------------------------------------------------------------
extern "C" void kernel_launch(void* const* d_in, const int* in_sizes, int n_in,
                              void* d_out, int out_size) {
    const float* x = (const float*)d_in[0];   // [256, 1024]
    const float* T = (const float*)d_in[1];   // [1024, 128, 16]
    float* out = (float*)d_out;               // [256, 1152]

    copy_kernel<<<256, 256>>>(x, out);
    dim3 gg(J_F / BN, N_SAMP / BM);           // (32, 4) = 128 blocks
    gemm_kernel<<<gg, 256>>>(x, T);
    pair_kernel<<<dim3(B_F, 8), 256>>>(out);
}

// round 6
// speedup vs baseline: 1.4672x; 1.4672x over previous
#include <cuda_runtime.h>
#include <cuda_bf16.h>
#include <cstdint>

#define N_SAMP 256
#define IN_F   1024
#define B_F    128
#define C_F    16
#define J_F    (B_F * C_F)   // 2048
#define OUT_W  (IN_F + B_F)  // 1152

// ---------------- scratch (no allocs allowed) ----------------
__device__ float          g_mat[B_F * N_SAMP * C_F];   // [b][n][c] fp32, 2MB
__device__ __nv_bfloat16  g_xb[N_SAMP * IN_F];         // x bf16 [256][1024]
__device__ __nv_bfloat16  g_Tt[J_F * IN_F];            // T^T bf16 [2048][1024]

__device__ __forceinline__ uint32_t smem_u32(const void* p) {
    uint32_t a;
    asm("{ .reg .u64 t; cvta.to.shared.u64 t, %1; cvt.u32.u64 %0, t; }" : "=r"(a) : "l"(p));
    return a;
}

// ---------------------------------------------------------------------------
// convert_x: x fp32 -> g_xb bf16, AND copy x into out[:,0:1024] (fused copy)
// ---------------------------------------------------------------------------
__global__ __launch_bounds__(256) void convert_x_kernel(const float* __restrict__ x,
                                                        float* __restrict__ out) {
    int idx = blockIdx.x * 256 + threadIdx.x;      // float4 index, 65536 total
    float4 v = ((const float4*)x)[idx];
    int n = idx >> 8, c4 = idx & 255;
    ((float4*)(out + n * OUT_W))[c4] = v;
    __nv_bfloat162* xb2 = (__nv_bfloat162*)g_xb;
    xb2[idx * 2 + 0] = __floats2bfloat162_rn(v.x, v.y);
    xb2[idx * 2 + 1] = __floats2bfloat162_rn(v.z, v.w);
}

// ---------------------------------------------------------------------------
// transpose T [1024][2048] fp32 -> g_Tt [2048][1024] bf16
// ---------------------------------------------------------------------------
__global__ __launch_bounds__(256) void transpose_T_kernel(const float* __restrict__ T) {
    __shared__ float s[32][33];
    const int tx = threadIdx.x, ty = threadIdx.y;     // (32, 8)
    const int bj = blockIdx.x * 32, bk = blockIdx.y * 32;
    #pragma unroll
    for (int i = 0; i < 4; i++)
        s[ty + i * 8][tx] = T[(bk + ty + i * 8) * J_F + bj + tx];
    __syncthreads();
    #pragma unroll
    for (int i = 0; i < 4; i++)
        g_Tt[(size_t)(bj + ty + i * 8) * IN_F + bk + tx] = __float2bfloat16(s[tx][ty + i * 8]);
}

// ---------------------------------------------------------------------------
// mma.sync bf16 GEMM: g_mat scatter of C[n][j] = sum_k xb[n][k] * Tt[j][k]
// BM=64, BN=128, BK=32; 8 warps as 2(M) x 4(N); warp tile 32x32;
// mma.sync.m16n8k16.row.col, A via ldmatrix.x4, B via direct 32-bit LDS.
// SMEM rows padded to 40 bf16 (80B = 20 banks) -> conflict-free.
// ---------------------------------------------------------------------------
#define GBM 64
#define GBN 128
#define GBK 32
#define KITERS (IN_F / GBK)   // 32

__global__ __launch_bounds__(256, 1) void gemm_mma_kernel() {
    __shared__ __nv_bfloat16 As[2][GBM][40];
    __shared__ __nv_bfloat16 Bs[2][GBN][40];

    const int tid  = threadIdx.x;
    const int wid  = tid >> 5;
    const int lane = tid & 31;
    const int bn   = blockIdx.x;       // 0..15
    const int bm   = blockIdx.y;       // 0..3
    const int wm   = wid >> 2;         // 0..1
    const int wn   = wid & 3;          // 0..3

    const __nv_bfloat16* Ab = g_xb + (size_t)(bm * GBM) * IN_F;
    const __nv_bfloat16* Bb = g_Tt + (size_t)(bn * GBN) * IN_F;

    // load mappings: 16B (8 bf16) per load
    const int lrow = tid >> 2;         // 0..63
    const int lseg = (tid & 3) * 8;    // 0,8,16,24

    float acc[2][4][4] = {};

    // prologue: stage 0
    {
        *(uint4*)&As[0][lrow][lseg] = *(const uint4*)(Ab + lrow * IN_F + lseg);
        *(uint4*)&Bs[0][lrow][lseg] = *(const uint4*)(Bb + lrow * IN_F + lseg);
        *(uint4*)&Bs[0][lrow + 64][lseg] = *(const uint4*)(Bb + (lrow + 64) * IN_F + lseg);
    }
    __syncthreads();

    for (int it = 0; it < KITERS; it++) {
        const int buf = it & 1;
        if (it + 1 < KITERS) {
            const int kt = (it + 1) * GBK;
            const int nb = buf ^ 1;
            *(uint4*)&As[nb][lrow][lseg] = *(const uint4*)(Ab + lrow * IN_F + kt + lseg);
            *(uint4*)&Bs[nb][lrow][lseg] = *(const uint4*)(Bb + lrow * IN_F + kt + lseg);
            *(uint4*)&Bs[nb][lrow + 64][lseg] = *(const uint4*)(Bb + (lrow + 64) * IN_F + kt + lseg);
        }

        #pragma unroll
        for (int ks = 0; ks < 2; ks++) {
            // A fragments: ldmatrix x4 per 16-row m-frag
            uint32_t a[2][4];
            const int sub  = lane >> 3;                    // 0..3
            const int arow = (sub & 1) * 8 + (lane & 7);   // row within frag
            const int acol = ks * 16 + (sub >> 1) * 8;     // k col
            #pragma unroll
            for (int mf = 0; mf < 2; mf++) {
                uint32_t addr = smem_u32(&As[buf][wm * 32 + mf * 16 + arow][acol]);
                asm volatile("ldmatrix.sync.aligned.m8n8.x4.shared.b16 {%0,%1,%2,%3}, [%4];"
                             : "=r"(a[mf][0]), "=r"(a[mf][1]), "=r"(a[mf][2]), "=r"(a[mf][3])
                             : "r"(addr));
            }
            // B fragments: thread t -> n = base + t/4, k pair at 2*(t%4)
            uint32_t b0[4], b1[4];
            #pragma unroll
            for (int nf = 0; nf < 4; nf++) {
                const __nv_bfloat16* p =
                    &Bs[buf][wn * 32 + nf * 8 + (lane >> 2)][ks * 16 + (lane & 3) * 2];
                b0[nf] = *(const uint32_t*)p;
                b1[nf] = *(const uint32_t*)(p + 8);
            }
            #pragma unroll
            for (int mf = 0; mf < 2; mf++)
                #pragma unroll
                for (int nf = 0; nf < 4; nf++)
                    asm volatile(
                        "mma.sync.aligned.m16n8k16.row.col.f32.bf16.bf16.f32 "
                        "{%0,%1,%2,%3}, {%4,%5,%6,%7}, {%8,%9}, {%0,%1,%2,%3};"
                        : "+f"(acc[mf][nf][0]), "+f"(acc[mf][nf][1]),
                          "+f"(acc[mf][nf][2]), "+f"(acc[mf][nf][3])
                        : "r"(a[mf][0]), "r"(a[mf][1]), "r"(a[mf][2]), "r"(a[mf][3]),
                          "r"(b0[nf]), "r"(b1[nf]));
        }
        __syncthreads();
    }

    // Epilogue: scatter into g_mat[b][n][c], b = j>>4, c = j&15
    // c0,c1: row g = lane/4, cols 2*(lane%4), +1; c2,c3: row g+8.
    const int g   = lane >> 2;
    const int cc  = (lane & 3) * 2;
    #pragma unroll
    for (int mf = 0; mf < 2; mf++) {
        const int row0 = bm * GBM + wm * 32 + mf * 16 + g;
        #pragma unroll
        for (int nf = 0; nf < 4; nf++) {
            const int j  = bn * GBN + wn * 32 + nf * 8 + cc;
            const int bb = j >> 4;
            const int c  = j & 15;
            float* dst = g_mat + bb * (N_SAMP * C_F);
            *(float2*)(dst + row0 * C_F + c) =
                make_float2(acc[mf][nf][0], acc[mf][nf][1]);
            *(float2*)(dst + (row0 + 8) * C_F + c) =
                make_float2(acc[mf][nf][2], acc[mf][nf][3]);
        }
    }
}

// ---------------------------------------------------------------------------
// Pairwise: o[n,b] = sum_m exp(-sum_c |mat[n,b,c]-mat[m,b,c]|)   (unchanged)
// ---------------------------------------------------------------------------
__global__ __launch_bounds__(256) void pair_kernel(float* __restrict__ out) {
    __shared__ float sm[N_SAMP][C_F];
    __shared__ float red[8][33];

    const int b   = blockIdx.x;
    const int nt  = blockIdx.y;
    const int tid = threadIdx.x;
    const float* mb = g_mat + b * (N_SAMP * C_F);

    #pragma unroll
    for (int r = 0; r < 4; r++) {
        int i = tid + r * 256;
        ((float4*)sm)[i] = ((const float4*)mb)[i];
    }
    __syncthreads();

    const int tn = tid & 31;
    const int tm = tid >> 5;
    const int n  = nt * 32 + tn;

    float mine[C_F];
    #pragma unroll
    for (int c = 0; c < C_F; c++) mine[c] = sm[n][c];

    float acc = 0.f;
    for (int m = tm; m < N_SAMP; m += 8) {
        const float4 v0 = *(const float4*)&sm[m][0];
        const float4 v1 = *(const float4*)&sm[m][4];
        const float4 v2 = *(const float4*)&sm[m][8];
        const float4 v3 = *(const float4*)&sm[m][12];
        float d = 0.f;
        d += fabsf(mine[0]  - v0.x); d += fabsf(mine[1]  - v0.y);
        d += fabsf(mine[2]  - v0.z); d += fabsf(mine[3]  - v0.w);
        d += fabsf(mine[4]  - v1.x); d += fabsf(mine[5]  - v1.y);
        d += fabsf(mine[6]  - v1.z); d += fabsf(mine[7]  - v1.w);
        d += fabsf(mine[8]  - v2.x); d += fabsf(mine[9]  - v2.y);
        d += fabsf(mine[10] - v2.z); d += fabsf(mine[11] - v2.w);
        d += fabsf(mine[12] - v3.x); d += fabsf(mine[13] - v3.y);
        d += fabsf(mine[14] - v3.z); d += fabsf(mine[15] - v3.w);
        if (d < 40.f) acc += __expf(-d);
    }
    red[tm][tn] = acc;
    __syncthreads();

    if (tm == 0) {
        float s = acc;
        #pragma unroll
        for (int t = 1; t < 8; t++) s += red[t][tn];
        out[n * OUT_W + IN_F + b] = s;
    }
}

// ---------------------------------------------------------------------------
extern "C" void kernel_launch(void* const* d_in, const int* in_sizes, int n_in,
                              void* d_out, int out_size) {
    const float* x = (const float*)d_in[0];   // [256, 1024]
    const float* T = (const float*)d_in[1];   // [1024, 128, 16]
    float* out = (float*)d_out;               // [256, 1152]

    convert_x_kernel<<<256, 256>>>(x, out);
    transpose_T_kernel<<<dim3(J_F / 32, IN_F / 32), dim3(32, 8)>>>(T);
    gemm_mma_kernel<<<dim3(J_F / GBN, N_SAMP / GBM), 256>>>();
    pair_kernel<<<dim3(B_F, 8), 256>>>(out);
}

// round 7
// speedup vs baseline: 1.6734x; 1.1405x over previous
#include <cuda_runtime.h>
#include <cuda_bf16.h>
#include <cstdint>

#define N_SAMP 256
#define IN_F   1024
#define B_F    128
#define C_F    16
#define J_F    (B_F * C_F)   // 2048
#define OUT_W  (IN_F + B_F)  // 1152

// ---------------- scratch (no allocs allowed) ----------------
__device__ float          g_mat[B_F * N_SAMP * C_F];   // [b][n][c] fp32, 2MB
__device__ __nv_bfloat16  g_xb[N_SAMP * IN_F];         // x bf16 [256][1024]
__device__ __nv_bfloat16  g_Tt[J_F * IN_F];            // T^T bf16 [2048][1024]

__device__ __forceinline__ uint32_t smem_u32(const void* p) {
    uint32_t a;
    asm("{ .reg .u64 t; cvta.to.shared.u64 t, %1; cvt.u32.u64 %0, t; }" : "=r"(a) : "l"(p));
    return a;
}

// ---------------------------------------------------------------------------
// convert_x: x fp32 -> g_xb bf16, AND copy x into out[:,0:1024] (fused copy)
// ---------------------------------------------------------------------------
__global__ __launch_bounds__(256) void convert_x_kernel(const float* __restrict__ x,
                                                        float* __restrict__ out) {
    int idx = blockIdx.x * 256 + threadIdx.x;      // float4 index, 65536 total
    float4 v = ((const float4*)x)[idx];
    int n = idx >> 8, c4 = idx & 255;
    ((float4*)(out + n * OUT_W))[c4] = v;
    __nv_bfloat162* xb2 = (__nv_bfloat162*)g_xb;
    xb2[idx * 2 + 0] = __floats2bfloat162_rn(v.x, v.y);
    xb2[idx * 2 + 1] = __floats2bfloat162_rn(v.z, v.w);
}

// ---------------------------------------------------------------------------
// transpose T [1024][2048] fp32 -> g_Tt [2048][1024] bf16
// ---------------------------------------------------------------------------
__global__ __launch_bounds__(256) void transpose_T_kernel(const float* __restrict__ T) {
    __shared__ float s[32][33];
    const int tx = threadIdx.x, ty = threadIdx.y;     // (32, 8)
    const int bj = blockIdx.x * 32, bk = blockIdx.y * 32;
    #pragma unroll
    for (int i = 0; i < 4; i++)
        s[ty + i * 8][tx] = T[(bk + ty + i * 8) * J_F + bj + tx];
    __syncthreads();
    #pragma unroll
    for (int i = 0; i < 4; i++)
        g_Tt[(size_t)(bj + ty + i * 8) * IN_F + bk + tx] = __float2bfloat16(s[tx][ty + i * 8]);
}

// ---------------------------------------------------------------------------
// mma.sync bf16 GEMM  (unchanged from R6)
// ---------------------------------------------------------------------------
#define GBM 64
#define GBN 128
#define GBK 32
#define KITERS (IN_F / GBK)   // 32

__global__ __launch_bounds__(256, 1) void gemm_mma_kernel() {
    __shared__ __nv_bfloat16 As[2][GBM][40];
    __shared__ __nv_bfloat16 Bs[2][GBN][40];

    const int tid  = threadIdx.x;
    const int wid  = tid >> 5;
    const int lane = tid & 31;
    const int bn   = blockIdx.x;       // 0..15
    const int bm   = blockIdx.y;       // 0..3
    const int wm   = wid >> 2;         // 0..1
    const int wn   = wid & 3;          // 0..3

    const __nv_bfloat16* Ab = g_xb + (size_t)(bm * GBM) * IN_F;
    const __nv_bfloat16* Bb = g_Tt + (size_t)(bn * GBN) * IN_F;

    const int lrow = tid >> 2;         // 0..63
    const int lseg = (tid & 3) * 8;    // 0,8,16,24

    float acc[2][4][4] = {};

    {
        *(uint4*)&As[0][lrow][lseg] = *(const uint4*)(Ab + lrow * IN_F + lseg);
        *(uint4*)&Bs[0][lrow][lseg] = *(const uint4*)(Bb + lrow * IN_F + lseg);
        *(uint4*)&Bs[0][lrow + 64][lseg] = *(const uint4*)(Bb + (lrow + 64) * IN_F + lseg);
    }
    __syncthreads();

    for (int it = 0; it < KITERS; it++) {
        const int buf = it & 1;
        if (it + 1 < KITERS) {
            const int kt = (it + 1) * GBK;
            const int nb = buf ^ 1;
            *(uint4*)&As[nb][lrow][lseg] = *(const uint4*)(Ab + lrow * IN_F + kt + lseg);
            *(uint4*)&Bs[nb][lrow][lseg] = *(const uint4*)(Bb + lrow * IN_F + kt + lseg);
            *(uint4*)&Bs[nb][lrow + 64][lseg] = *(const uint4*)(Bb + (lrow + 64) * IN_F + kt + lseg);
        }

        #pragma unroll
        for (int ks = 0; ks < 2; ks++) {
            uint32_t a[2][4];
            const int sub  = lane >> 3;
            const int arow = (sub & 1) * 8 + (lane & 7);
            const int acol = ks * 16 + (sub >> 1) * 8;
            #pragma unroll
            for (int mf = 0; mf < 2; mf++) {
                uint32_t addr = smem_u32(&As[buf][wm * 32 + mf * 16 + arow][acol]);
                asm volatile("ldmatrix.sync.aligned.m8n8.x4.shared.b16 {%0,%1,%2,%3}, [%4];"
                             : "=r"(a[mf][0]), "=r"(a[mf][1]), "=r"(a[mf][2]), "=r"(a[mf][3])
                             : "r"(addr));
            }
            uint32_t b0[4], b1[4];
            #pragma unroll
            for (int nf = 0; nf < 4; nf++) {
                const __nv_bfloat16* p =
                    &Bs[buf][wn * 32 + nf * 8 + (lane >> 2)][ks * 16 + (lane & 3) * 2];
                b0[nf] = *(const uint32_t*)p;
                b1[nf] = *(const uint32_t*)(p + 8);
            }
            #pragma unroll
            for (int mf = 0; mf < 2; mf++)
                #pragma unroll
                for (int nf = 0; nf < 4; nf++)
                    asm volatile(
                        "mma.sync.aligned.m16n8k16.row.col.f32.bf16.bf16.f32 "
                        "{%0,%1,%2,%3}, {%4,%5,%6,%7}, {%8,%9}, {%0,%1,%2,%3};"
                        : "+f"(acc[mf][nf][0]), "+f"(acc[mf][nf][1]),
                          "+f"(acc[mf][nf][2]), "+f"(acc[mf][nf][3])
                        : "r"(a[mf][0]), "r"(a[mf][1]), "r"(a[mf][2]), "r"(a[mf][3]),
                          "r"(b0[nf]), "r"(b1[nf]));
        }
        __syncthreads();
    }

    const int g   = lane >> 2;
    const int cc  = (lane & 3) * 2;
    #pragma unroll
    for (int mf = 0; mf < 2; mf++) {
        const int row0 = bm * GBM + wm * 32 + mf * 16 + g;
        #pragma unroll
        for (int nf = 0; nf < 4; nf++) {
            const int j  = bn * GBN + wn * 32 + nf * 8 + cc;
            const int bb = j >> 4;
            const int c  = j & 15;
            float* dst = g_mat + bb * (N_SAMP * C_F);
            *(float2*)(dst + row0 * C_F + c) =
                make_float2(acc[mf][nf][0], acc[mf][nf][1]);
            *(float2*)(dst + (row0 + 8) * C_F + c) =
                make_float2(acc[mf][nf][2], acc[mf][nf][3]);
        }
    }
}

// ---------------------------------------------------------------------------
// Pairwise with triangle-inequality pruning.
// For groups g of 4 channels: d(n,m) >= sum_g |sg(n) - sg(m)|  (exact bound).
// Only pairs whose bound < 40 get the full 16-element distance; all other
// pairs have exp(-d) <= exp(-40) ~ 4e-18, negligible (and were skipped by
// the previous kernel's d<40 guard too). Threads: 512 = 256 n x 2 m-halves.
// ---------------------------------------------------------------------------
__global__ __launch_bounds__(512) void pair_kernel(float* __restrict__ out) {
    __shared__ float  sm[N_SAMP][C_F];    // 16 KB
    __shared__ float4 sgrp[N_SAMP];       // 4 KB group sums
    __shared__ float  part[N_SAMP];       // 1 KB half-1 partials

    const int b   = blockIdx.x;
    const int tid = threadIdx.x;
    const float* mb = g_mat + b * (N_SAMP * C_F);

    #pragma unroll
    for (int r = 0; r < 2; r++) {
        int i = tid + r * 512;            // float4 index, 1024 total
        ((float4*)sm)[i] = ((const float4*)mb)[i];
    }
    __syncthreads();

    const int n    = tid & 255;
    const int half = tid >> 8;

    // own row + group sums
    const float4 a0 = *(const float4*)&sm[n][0];
    const float4 a1 = *(const float4*)&sm[n][4];
    const float4 a2 = *(const float4*)&sm[n][8];
    const float4 a3 = *(const float4*)&sm[n][12];
    const float4 myg = make_float4(a0.x + a0.y + a0.z + a0.w,
                                   a1.x + a1.y + a1.z + a1.w,
                                   a2.x + a2.y + a2.z + a2.w,
                                   a3.x + a3.y + a3.z + a3.w);
    if (half == 0) sgrp[n] = myg;
    __syncthreads();

    float acc = 0.f;
    const int m0 = half * 128;
    #pragma unroll 4
    for (int m = m0; m < m0 + 128; m++) {
        const float4 s = sgrp[m];          // broadcast
        const float bnd = fabsf(myg.x - s.x) + fabsf(myg.y - s.y) +
                          fabsf(myg.z - s.z) + fabsf(myg.w - s.w);
        if (__any_sync(0xFFFFFFFFu, bnd < 40.f)) {
            const float4 v0 = *(const float4*)&sm[m][0];
            const float4 v1 = *(const float4*)&sm[m][4];
            const float4 v2 = *(const float4*)&sm[m][8];
            const float4 v3 = *(const float4*)&sm[m][12];
            float d = 0.f;
            d += fabsf(a0.x - v0.x); d += fabsf(a0.y - v0.y);
            d += fabsf(a0.z - v0.z); d += fabsf(a0.w - v0.w);
            d += fabsf(a1.x - v1.x); d += fabsf(a1.y - v1.y);
            d += fabsf(a1.z - v1.z); d += fabsf(a1.w - v1.w);
            d += fabsf(a2.x - v2.x); d += fabsf(a2.y - v2.y);
            d += fabsf(a2.z - v2.z); d += fabsf(a2.w - v2.w);
            d += fabsf(a3.x - v3.x); d += fabsf(a3.y - v3.y);
            d += fabsf(a3.z - v3.z); d += fabsf(a3.w - v3.w);
            acc += __expf(-d);             // self term exp(0)=1; d>=40 -> ~0
        }
    }

    if (half == 1) part[n] = acc;
    __syncthreads();
    if (half == 0)
        out[n * OUT_W + IN_F + b] = acc + part[n];
}

// ---------------------------------------------------------------------------
extern "C" void kernel_launch(void* const* d_in, const int* in_sizes, int n_in,
                              void* d_out, int out_size) {
    const float* x = (const float*)d_in[0];   // [256, 1024]
    const float* T = (const float*)d_in[1];   // [1024, 128, 16]
    float* out = (float*)d_out;               // [256, 1152]

    convert_x_kernel<<<256, 256>>>(x, out);
    transpose_T_kernel<<<dim3(J_F / 32, IN_F / 32), dim3(32, 8)>>>(T);
    gemm_mma_kernel<<<dim3(J_F / GBN, N_SAMP / GBM), 256>>>();
    pair_kernel<<<B_F, 512>>>(out);
}